// round 15
// baseline (speedup 1.0000x reference)
#include <cuda_runtime.h>

// LSTMAutoencoder: B=4096, T=512, F=8, H=16
// enc LSTM -> hT -> repeat -> dec LSTM -> fused linear
//
// R14 = R11 layout (CH=4 chains per 16-lane group, 2 groups x 4 chains = 8
// elements per 32-thread block, 512 single-warp blocks -> every warp on its
// own SMSP, zero wave tail) + R12's xproj tail-fill (encoder input
// projection for step t+1 computed between the STS and __syncwarp of step
// t: 64 h-independent FFMA2s covering the MUFU epilogue + barrier + LDS
// latency). tanh.approx activations (sigmoid(z)=0.5+0.5*tanh(z/2), the 1/2
// folded into i/f/o weight rows); biases folded; decoder input projection
// hoisted; output linear fused into decoder steps; 1-step-lookahead x
// prefetch (LDG has a full ~600-cycle step to complete).

using ull = unsigned long long;

#define Bsz 4096
#define Tsz 512
#define Fsz 8
#define Hsz 16
#define CH 4
#define GPB 2
#define EPB (GPB * CH)          // 8 elements per block
#define THREADS (GPB * 16)      // 32
#define XSTRIDE (Tsz * Fsz / 4) // longlong2 units per element
#define OSTRIDE (Tsz * Fsz)

__device__ __forceinline__ void fma2(ull& d, ull a, ull b) {
    asm("fma.rn.f32x2 %0, %1, %2, %0;" : "+l"(d) : "l"(a), "l"(b));
}
__device__ __forceinline__ ull fma2a(ull a, ull b, ull c) {
    ull r; asm("fma.rn.f32x2 %0, %1, %2, %3;" : "=l"(r) : "l"(a), "l"(b), "l"(c)); return r;
}
__device__ __forceinline__ ull mul2(ull a, ull b) {
    ull r; asm("mul.rn.f32x2 %0, %1, %2;" : "=l"(r) : "l"(a), "l"(b)); return r;
}
__device__ __forceinline__ ull pk(float lo, float hi) {
    ull r; asm("mov.b64 %0, {%1, %2};" : "=l"(r) : "f"(lo), "f"(hi)); return r;
}
__device__ __forceinline__ float redu(ull a) {   // lo + hi
    float lo, hi; asm("mov.b64 {%0, %1}, %2;" : "=f"(lo), "=f"(hi) : "l"(a));
    return lo + hi;
}
__device__ __forceinline__ float tanha(float x){
    float y; asm("tanh.approx.f32 %0, %1;" : "=f"(y) : "f"(x)); return y;
}

__global__ void __launch_bounds__(THREADS, 4)
lstm_ae(const float* __restrict__ x,
        const float* __restrict__ eWih, const float* __restrict__ eWhh,
        const float* __restrict__ eBih, const float* __restrict__ eBhh,
        const float* __restrict__ dWih, const float* __restrict__ dWhh,
        const float* __restrict__ dBih, const float* __restrict__ dBhh,
        const float* __restrict__ oW,  const float* __restrict__ oB,
        float* __restrict__ out)
{
    __shared__ __align__(16) float hbuf[2][EPB][Hsz];
    const int j   = threadIdx.x & 15;
    const int grp = threadIdx.x >> 4;      // 0..1
    const int e0  = grp * CH;
    const long b0 = (long)blockIdx.x * EPB + e0;

    const ull scH = pk(0.5f, 0.5f);        // sigmoid-as-tanh arg scale

    // ---------------- encoder weights (pre-scaled, packed; shared by chains)
    ull whh[4][8];
    ull wih[4][4];
    ull biaspk[4];
    #pragma unroll
    for (int g = 0; g < 4; ++g) {
        const bool isG = (g == 2);
        const float scf = isG ? 1.0f : 0.5f;
        const int row = g * Hsz + j;
        const ull* wr = reinterpret_cast<const ull*>(eWhh + row * Hsz);
        #pragma unroll
        for (int p = 0; p < 8; ++p) whh[g][p] = isG ? wr[p] : mul2(wr[p], scH);
        const ull* wi = reinterpret_cast<const ull*>(eWih + row * Fsz);
        #pragma unroll
        for (int p = 0; p < 4; ++p) wih[g][p] = isG ? wi[p] : mul2(wi[p], scH);
        biaspk[g] = pk(scf * (eBih[row] + eBhh[row]), 0.0f);
    }

    #pragma unroll
    for (int u = 0; u < CH; ++u) hbuf[0][e0 + u][j] = 0.0f;
    __syncwarp();

    const longlong2* px = reinterpret_cast<const longlong2*>(x + b0 * Tsz * Fsz);
    float cs[CH] = {0.0f, 0.0f, 0.0f, 0.0f};

    ull xv[CH][4];   // staged x(t+1) (prefetched)
    ull xp[CH][4];   // precomputed input projection for the upcoming step

    auto ldx = [&](int t) {
        #pragma unroll
        for (int u = 0; u < CH; ++u) {
            longlong2 a = px[u * XSTRIDE + 2 * t], b2 = px[u * XSTRIDE + 2 * t + 1];
            xv[u][0] = (ull)a.x; xv[u][1] = (ull)a.y;
            xv[u][2] = (ull)b2.x; xv[u][3] = (ull)b2.y;
        }
    };
    auto xproj = [&]() {    // xp[u][g] = bias_g + Wih_g . xv_u  (h-free FFMA)
        #pragma unroll
        for (int u = 0; u < CH; ++u) {
            #pragma unroll
            for (int g = 0; g < 4; ++g) {
                ull a = fma2a(wih[g][0], xv[u][0], biaspk[g]);
                fma2(a, wih[g][1], xv[u][1]);
                fma2(a, wih[g][2], xv[u][2]);
                fma2(a, wih[g][3], xv[u][3]);
                xp[u][g] = a;
            }
        }
    };

    // gate epilogue: 4 pre-activations -> new h (5 MUFU.TANH)
    auto gates = [&](ull a0, ull a1, ull a2, ull a3, float& c) -> float {
        const float ti = tanha(redu(a0));
        const float tf = tanha(redu(a1));
        const float tg = tanha(redu(a2));
        const float to = tanha(redu(a3));
        const float gi = fmaf(ti, 0.5f, 0.5f);
        const float gf = fmaf(tf, 0.5f, 0.5f);
        const float go = fmaf(to, 0.5f, 0.5f);
        c = fmaf(gf, c, gi * tg);
        return go * tanha(c);
    };

    // encoder step: consumes xp (= proj of x(t)); after the STS and BEFORE
    // the barrier, recomputes xp from xv (= x(t+1)) and prefetches x(t+2).
    auto estep = [&](int rb, int tload) {
        float hh[CH];
        #pragma unroll
        for (int u = 0; u < CH; ++u) {
            const longlong2* hr = reinterpret_cast<const longlong2*>(&hbuf[rb][e0 + u][0]);
            longlong2 H0 = hr[0], H1 = hr[1], H2 = hr[2], H3 = hr[3];
            ull h0 = (ull)H0.x, h1 = (ull)H0.y, h2 = (ull)H1.x, h3 = (ull)H1.y,
                h4 = (ull)H2.x, h5 = (ull)H2.y, h6 = (ull)H3.x, h7 = (ull)H3.y;
            ull a0 = fma2a(whh[0][0], h0, xp[u][0]);
            ull a1 = fma2a(whh[1][0], h0, xp[u][1]);
            ull a2 = fma2a(whh[2][0], h0, xp[u][2]);
            ull a3 = fma2a(whh[3][0], h0, xp[u][3]);
            fma2(a0, whh[0][1], h1); fma2(a1, whh[1][1], h1);
            fma2(a2, whh[2][1], h1); fma2(a3, whh[3][1], h1);
            fma2(a0, whh[0][2], h2); fma2(a1, whh[1][2], h2);
            fma2(a2, whh[2][2], h2); fma2(a3, whh[3][2], h2);
            fma2(a0, whh[0][3], h3); fma2(a1, whh[1][3], h3);
            fma2(a2, whh[2][3], h3); fma2(a3, whh[3][3], h3);
            fma2(a0, whh[0][4], h4); fma2(a1, whh[1][4], h4);
            fma2(a2, whh[2][4], h4); fma2(a3, whh[3][4], h4);
            fma2(a0, whh[0][5], h5); fma2(a1, whh[1][5], h5);
            fma2(a2, whh[2][5], h5); fma2(a3, whh[3][5], h5);
            fma2(a0, whh[0][6], h6); fma2(a1, whh[1][6], h6);
            fma2(a2, whh[2][6], h6); fma2(a3, whh[3][6], h6);
            fma2(a0, whh[0][7], h7); fma2(a1, whh[1][7], h7);
            fma2(a2, whh[2][7], h7); fma2(a3, whh[3][7], h7);
            hh[u] = gates(a0, a1, a2, a3, cs[u]);
        }
        #pragma unroll
        for (int u = 0; u < CH; ++u) hbuf[rb ^ 1][e0 + u][j] = hh[u];
        xproj();                          // proj of x(t+1): fills MUFU tail
        if (tload < Tsz) ldx(tload);      // prefetch x(t+2)
        __syncwarp();
    };

    // prologue: xp = proj x(0); xv = x(1)
    ldx(0); xproj(); ldx(1);

    #pragma unroll 1
    for (int t = 0; t < Tsz; t += 2) {
        estep(0, t + 2);
        estep(1, t + 3);
    }
    // hT for all chains in hbuf[0]

    // ---------------- decoder prep ----------------
    ull xpdpk[CH][4];
    #pragma unroll
    for (int g = 0; g < 4; ++g) {
        const bool isG = (g == 2);
        const float scf = isG ? 1.0f : 0.5f;
        const int row = g * Hsz + j;
        const float bsum = scf * (dBih[row] + dBhh[row]);
        const ull* wr = reinterpret_cast<const ull*>(dWih + row * Hsz);
        #pragma unroll
        for (int u = 0; u < CH; ++u) {
            const ull* hr0 = reinterpret_cast<const ull*>(&hbuf[0][e0 + u][0]);
            ull acc = pk(bsum, 0.0f);
            #pragma unroll
            for (int p = 0; p < 8; ++p) {
                ull w = isG ? wr[p] : mul2(wr[p], scH);
                fma2(acc, w, hr0[p]);
            }
            xpdpk[u][g] = pk(redu(acc), 0.0f);
        }
        const ull* wh = reinterpret_cast<const ull*>(dWhh + row * Hsz);
        #pragma unroll
        for (int p = 0; p < 8; ++p) whh[g][p] = isG ? wh[p] : mul2(wh[p], scH);
    }
    ull owp[8];
    const int f = j & 7;
    {
        const ull* orow = reinterpret_cast<const ull*>(oW + f * Hsz);
        #pragma unroll
        for (int p = 0; p < 8; ++p) owp[p] = orow[p];
    }
    const ull outbpk = pk(oB[f], 0.0f);

    #pragma unroll
    for (int u = 0; u < CH; ++u) cs[u] = 0.0f;
    __syncwarp();                 // all lanes done reading hT
    #pragma unroll
    for (int u = 0; u < CH; ++u) hbuf[0][e0 + u][j] = 0.0f;
    __syncwarp();

    float* po = out + b0 * Tsz * Fsz + f;   // chain u at po[u*OSTRIDE]

    // decoder step: reads h_{t-1}; when doOut, emits output row for t-1
    // reusing the same h loads, then computes h_t.
    auto dstep = [&](int rb, bool doOut) {
        float hh[CH];
        #pragma unroll
        for (int u = 0; u < CH; ++u) {
            const longlong2* hr = reinterpret_cast<const longlong2*>(&hbuf[rb][e0 + u][0]);
            longlong2 H0 = hr[0], H1 = hr[1], H2 = hr[2], H3 = hr[3];
            ull h0 = (ull)H0.x, h1 = (ull)H0.y, h2 = (ull)H1.x, h3 = (ull)H1.y,
                h4 = (ull)H2.x, h5 = (ull)H2.y, h6 = (ull)H3.x, h7 = (ull)H3.y;
            if (doOut) {
                ull oacc = fma2a(owp[0], h0, outbpk);
                fma2(oacc, owp[1], h1); fma2(oacc, owp[2], h2);
                fma2(oacc, owp[3], h3); fma2(oacc, owp[4], h4);
                fma2(oacc, owp[5], h5); fma2(oacc, owp[6], h6);
                fma2(oacc, owp[7], h7);
                if (j < 8) po[u * OSTRIDE] = redu(oacc);
            }
            ull a0 = fma2a(whh[0][0], h0, xpdpk[u][0]);
            ull a1 = fma2a(whh[1][0], h0, xpdpk[u][1]);
            ull a2 = fma2a(whh[2][0], h0, xpdpk[u][2]);
            ull a3 = fma2a(whh[3][0], h0, xpdpk[u][3]);
            fma2(a0, whh[0][1], h1); fma2(a1, whh[1][1], h1);
            fma2(a2, whh[2][1], h1); fma2(a3, whh[3][1], h1);
            fma2(a0, whh[0][2], h2); fma2(a1, whh[1][2], h2);
            fma2(a2, whh[2][2], h2); fma2(a3, whh[3][2], h2);
            fma2(a0, whh[0][3], h3); fma2(a1, whh[1][3], h3);
            fma2(a2, whh[2][3], h3); fma2(a3, whh[3][3], h3);
            fma2(a0, whh[0][4], h4); fma2(a1, whh[1][4], h4);
            fma2(a2, whh[2][4], h4); fma2(a3, whh[3][4], h4);
            fma2(a0, whh[0][5], h5); fma2(a1, whh[1][5], h5);
            fma2(a2, whh[2][5], h5); fma2(a3, whh[3][5], h5);
            fma2(a0, whh[0][6], h6); fma2(a1, whh[1][6], h6);
            fma2(a2, whh[2][6], h6); fma2(a3, whh[3][6], h6);
            fma2(a0, whh[0][7], h7); fma2(a1, whh[1][7], h7);
            fma2(a2, whh[2][7], h7); fma2(a3, whh[3][7], h7);
            hh[u] = gates(a0, a1, a2, a3, cs[u]);
        }
        if (doOut) po += Fsz;
        #pragma unroll
        for (int u = 0; u < CH; ++u) hbuf[rb ^ 1][e0 + u][j] = hh[u];
        __syncwarp();
    };

    dstep(0, false);   // t=0 (no previous h to emit)
    dstep(1, true);    // t=1, emits row 0
    #pragma unroll 1
    for (int t = 2; t < Tsz; t += 2) {
        dstep(0, true);
        dstep(1, true);
    }
    // emit final row (h_{511} in hbuf[0])
    #pragma unroll
    for (int u = 0; u < CH; ++u) {
        const ull* hr = reinterpret_cast<const ull*>(&hbuf[0][e0 + u][0]);
        ull oacc = fma2a(owp[0], hr[0], outbpk);
        #pragma unroll
        for (int p = 1; p < 8; ++p) fma2(oacc, owp[p], hr[p]);
        if (j < 8) po[u * OSTRIDE] = redu(oacc);
    }
}

extern "C" void kernel_launch(void* const* d_in, const int* in_sizes, int n_in,
                              void* d_out, int out_size) {
    (void)in_sizes; (void)n_in; (void)out_size;
    lstm_ae<<<Bsz / EPB, THREADS>>>(
        (const float*)d_in[0],
        (const float*)d_in[1], (const float*)d_in[2],
        (const float*)d_in[3], (const float*)d_in[4],
        (const float*)d_in[5], (const float*)d_in[6],
        (const float*)d_in[7], (const float*)d_in[8],
        (const float*)d_in[9], (const float*)d_in[10],
        (float*)d_out);
}

// round 16
// speedup vs baseline: 1.4932x; 1.4932x over previous
#include <cuda_runtime.h>

// LSTMAutoencoder: B=4096, T=512, F=8, H=16
// enc LSTM -> hT -> repeat -> dec LSTM -> fused linear
//
// R16 = R12 (355us best) + decoder tail-fill.
// Config: 16 lanes/element, CH=2 chains per lane group, 32-thread blocks,
// 1024 single-warp blocks (1.73 warps/SMSP), tanh.approx activations
// (sigmoid(z)=0.5+0.5*tanh(z/2), 1/2 folded into i/f/o weight rows),
// 2-step-lookahead double-buffered x prefetch, encoder xproj computed in
// the post-STS/pre-barrier tail (fills MUFU epilogue), even/odd tree
// accumulators (h-dependent FFMA2 chain depth 4).
// NEW: decoder output-linear for step t-1 moved from the step front into
// the post-STS/pre-barrier tail (h(t-1) regs still live) — same trick,
// fills the decoder's MUFU tail; recurrence FFMAs now start right after
// the LDS.

using ull = unsigned long long;

#define Bsz 4096
#define Tsz 512
#define Fsz 8
#define Hsz 16
#define CH 2
#define GPB 2
#define EPB (GPB * CH)          // 4 elements per block
#define THREADS (GPB * 16)      // 32
#define XSTRIDE (Tsz * Fsz / 4) // longlong2 units per element
#define OSTRIDE (Tsz * Fsz)

__device__ __forceinline__ void fma2(ull& d, ull a, ull b) {
    asm("fma.rn.f32x2 %0, %1, %2, %0;" : "+l"(d) : "l"(a), "l"(b));
}
__device__ __forceinline__ ull fma2a(ull a, ull b, ull c) {
    ull r; asm("fma.rn.f32x2 %0, %1, %2, %3;" : "=l"(r) : "l"(a), "l"(b), "l"(c)); return r;
}
__device__ __forceinline__ ull mul2(ull a, ull b) {
    ull r; asm("mul.rn.f32x2 %0, %1, %2;" : "=l"(r) : "l"(a), "l"(b)); return r;
}
__device__ __forceinline__ ull add2(ull a, ull b) {
    ull r; asm("add.rn.f32x2 %0, %1, %2;" : "=l"(r) : "l"(a), "l"(b)); return r;
}
__device__ __forceinline__ ull pk(float lo, float hi) {
    ull r; asm("mov.b64 %0, {%1, %2};" : "=l"(r) : "f"(lo), "f"(hi)); return r;
}
__device__ __forceinline__ float redu(ull a) {   // lo + hi
    float lo, hi; asm("mov.b64 {%0, %1}, %2;" : "=f"(lo), "=f"(hi) : "l"(a));
    return lo + hi;
}
__device__ __forceinline__ float tanha(float x){
    float y; asm("tanh.approx.f32 %0, %1;" : "=f"(y) : "f"(x)); return y;
}

__global__ void __launch_bounds__(THREADS, 8)
lstm_ae(const float* __restrict__ x,
        const float* __restrict__ eWih, const float* __restrict__ eWhh,
        const float* __restrict__ eBih, const float* __restrict__ eBhh,
        const float* __restrict__ dWih, const float* __restrict__ dWhh,
        const float* __restrict__ dBih, const float* __restrict__ dBhh,
        const float* __restrict__ oW,  const float* __restrict__ oB,
        float* __restrict__ out)
{
    __shared__ __align__(16) float hbuf[2][EPB][Hsz];
    const int j   = threadIdx.x & 15;
    const int grp = threadIdx.x >> 4;      // 0..1
    const int e0  = grp * CH;
    const long b0 = (long)blockIdx.x * EPB + e0;

    const ull scH = pk(0.5f, 0.5f);        // sigmoid-as-tanh arg scale

    // ---------------- encoder weights (pre-scaled, packed; shared by chains)
    ull whh[4][8];
    ull wih[4][4];
    ull biaspk[4];
    #pragma unroll
    for (int g = 0; g < 4; ++g) {
        const bool isG = (g == 2);
        const float scf = isG ? 1.0f : 0.5f;
        const int row = g * Hsz + j;
        const ull* wr = reinterpret_cast<const ull*>(eWhh + row * Hsz);
        #pragma unroll
        for (int p = 0; p < 8; ++p) whh[g][p] = isG ? wr[p] : mul2(wr[p], scH);
        const ull* wi = reinterpret_cast<const ull*>(eWih + row * Fsz);
        #pragma unroll
        for (int p = 0; p < 4; ++p) wih[g][p] = isG ? wi[p] : mul2(wi[p], scH);
        biaspk[g] = pk(scf * (eBih[row] + eBhh[row]), 0.0f);
    }

    #pragma unroll
    for (int u = 0; u < CH; ++u) hbuf[0][e0 + u][j] = 0.0f;
    __syncwarp();

    const longlong2* px = reinterpret_cast<const longlong2*>(x + b0 * Tsz * Fsz);
    float cs[CH] = {0.0f, 0.0f};

    // load x(t) for all chains into regs
    auto ldx = [&](ull d[CH][4], int t) {
        #pragma unroll
        for (int u = 0; u < CH; ++u) {
            longlong2 a = px[u * XSTRIDE + 2 * t], b2 = px[u * XSTRIDE + 2 * t + 1];
            d[u][0] = (ull)a.x; d[u][1] = (ull)a.y;
            d[u][2] = (ull)b2.x; d[u][3] = (ull)b2.y;
        }
    };

    // x-projection: xp[u][g] = bias_g + Wih_g . x_u   (pure FFMA, h-free)
    auto xproj = [&](ull xp[CH][4], ull xv[CH][4]) {
        #pragma unroll
        for (int u = 0; u < CH; ++u) {
            #pragma unroll
            for (int g = 0; g < 4; ++g) {
                ull a = fma2a(wih[g][0], xv[u][0], biaspk[g]);
                fma2(a, wih[g][1], xv[u][1]);
                fma2(a, wih[g][2], xv[u][2]);
                fma2(a, wih[g][3], xv[u][3]);
                xp[u][g] = a;
            }
        }
    };

    // gate epilogue: 4 pre-activations -> new h (5 MUFU.TANH)
    auto gates = [&](ull a0, ull a1, ull a2, ull a3, float& c) -> float {
        const float ti = tanha(redu(a0));
        const float tf = tanha(redu(a1));
        const float tg = tanha(redu(a2));
        const float to = tanha(redu(a3));
        const float gi = fmaf(ti, 0.5f, 0.5f);
        const float gf = fmaf(tf, 0.5f, 0.5f);
        const float go = fmaf(to, 0.5f, 0.5f);
        c = fmaf(gf, c, gi * tg);
        return go * tanha(c);
    };

    // encoder step: consumes xp (projection of x(t)); after storing h and
    // BEFORE the barrier, recomputes xp from xv (= x(t+2)) and reloads xv.
    auto estep = [&](int rb, ull xp[CH][4], ull xv[CH][4], int tload) {
        float hh[CH];
        #pragma unroll
        for (int u = 0; u < CH; ++u) {
            const longlong2* hr = reinterpret_cast<const longlong2*>(&hbuf[rb][e0 + u][0]);
            longlong2 H0 = hr[0], H1 = hr[1], H2 = hr[2], H3 = hr[3];
            ull h0 = (ull)H0.x, h1 = (ull)H0.y, h2 = (ull)H1.x, h3 = (ull)H1.y,
                h4 = (ull)H2.x, h5 = (ull)H2.y, h6 = (ull)H3.x, h7 = (ull)H3.y;
            // even tree seeded from precomputed xp; odd tree fresh
            ull a0 = fma2a(whh[0][0], h0, xp[u][0]);
            ull a1 = fma2a(whh[1][0], h0, xp[u][1]);
            ull a2 = fma2a(whh[2][0], h0, xp[u][2]);
            ull a3 = fma2a(whh[3][0], h0, xp[u][3]);
            ull b0a = mul2(whh[0][1], h1), b1a = mul2(whh[1][1], h1),
                b2a = mul2(whh[2][1], h1), b3a = mul2(whh[3][1], h1);
            fma2(a0, whh[0][2], h2); fma2(a1, whh[1][2], h2);
            fma2(a2, whh[2][2], h2); fma2(a3, whh[3][2], h2);
            fma2(b0a, whh[0][3], h3); fma2(b1a, whh[1][3], h3);
            fma2(b2a, whh[2][3], h3); fma2(b3a, whh[3][3], h3);
            fma2(a0, whh[0][4], h4); fma2(a1, whh[1][4], h4);
            fma2(a2, whh[2][4], h4); fma2(a3, whh[3][4], h4);
            fma2(b0a, whh[0][5], h5); fma2(b1a, whh[1][5], h5);
            fma2(b2a, whh[2][5], h5); fma2(b3a, whh[3][5], h5);
            fma2(a0, whh[0][6], h6); fma2(a1, whh[1][6], h6);
            fma2(a2, whh[2][6], h6); fma2(a3, whh[3][6], h6);
            fma2(b0a, whh[0][7], h7); fma2(b1a, whh[1][7], h7);
            fma2(b2a, whh[2][7], h7); fma2(b3a, whh[3][7], h7);
            hh[u] = gates(add2(a0, b0a), add2(a1, b1a),
                          add2(a2, b2a), add2(a3, b3a), cs[u]);
        }
        #pragma unroll
        for (int u = 0; u < CH; ++u) hbuf[rb ^ 1][e0 + u][j] = hh[u];
        // tail filler: next-next step's x projection (h-independent FFMAs)
        xproj(xp, xv);
        if (tload < Tsz) ldx(xv, tload);
        __syncwarp();
    };

    // prologue: xpA/xpB = proj of x(0)/x(1); xv/xn = x(2)/x(3)
    ull xv[CH][4], xn[CH][4], xpA[CH][4], xpB[CH][4];
    ldx(xv, 0); ldx(xn, 1);
    xproj(xpA, xv); xproj(xpB, xn);
    ldx(xv, 2); ldx(xn, 3);

    #pragma unroll 1
    for (int t = 0; t < Tsz; t += 2) {
        estep(0, xpA, xv, t + 4);    // consumes xpA(t),   rebuilds xpA(t+2)
        estep(1, xpB, xn, t + 5);    // consumes xpB(t+1), rebuilds xpB(t+3)
    }
    // hT for both chains in hbuf[0]

    // ---------------- decoder prep ----------------
    ull xpdpk[CH][4];
    #pragma unroll
    for (int g = 0; g < 4; ++g) {
        const bool isG = (g == 2);
        const float scf = isG ? 1.0f : 0.5f;
        const int row = g * Hsz + j;
        const float bsum = scf * (dBih[row] + dBhh[row]);
        const ull* wr = reinterpret_cast<const ull*>(dWih + row * Hsz);
        #pragma unroll
        for (int u = 0; u < CH; ++u) {
            const ull* hr0 = reinterpret_cast<const ull*>(&hbuf[0][e0 + u][0]);
            ull acc = pk(bsum, 0.0f);
            #pragma unroll
            for (int p = 0; p < 8; ++p) {
                ull w = isG ? wr[p] : mul2(wr[p], scH);
                fma2(acc, w, hr0[p]);
            }
            xpdpk[u][g] = pk(redu(acc), 0.0f);
        }
        const ull* wh = reinterpret_cast<const ull*>(dWhh + row * Hsz);
        #pragma unroll
        for (int p = 0; p < 8; ++p) whh[g][p] = isG ? wh[p] : mul2(wh[p], scH);
    }
    ull owp[8];
    const int f = j & 7;
    {
        const ull* orow = reinterpret_cast<const ull*>(oW + f * Hsz);
        #pragma unroll
        for (int p = 0; p < 8; ++p) owp[p] = orow[p];
    }
    const ull outbpk = pk(oB[f], 0.0f);

    cs[0] = 0.0f; cs[1] = 0.0f;
    __syncwarp();                 // all lanes done reading hT
    #pragma unroll
    for (int u = 0; u < CH; ++u) hbuf[0][e0 + u][j] = 0.0f;
    __syncwarp();

    float* po = out + b0 * Tsz * Fsz + f;   // chain u at po[u*OSTRIDE]

    // decoder step: reads h_{t-1}, computes h_t; when doOut, the output row
    // for t-1 is computed IN THE TAIL (after the STS of h_t, before the
    // barrier) from the still-live h(t-1) registers — fills the MUFU tail.
    auto dstep = [&](int rb, bool doOut) {
        float hh[CH];
        ull hs[CH][8];
        #pragma unroll
        for (int u = 0; u < CH; ++u) {
            const longlong2* hr = reinterpret_cast<const longlong2*>(&hbuf[rb][e0 + u][0]);
            longlong2 H0 = hr[0], H1 = hr[1], H2 = hr[2], H3 = hr[3];
            ull h0 = (ull)H0.x, h1 = (ull)H0.y, h2 = (ull)H1.x, h3 = (ull)H1.y,
                h4 = (ull)H2.x, h5 = (ull)H2.y, h6 = (ull)H3.x, h7 = (ull)H3.y;
            hs[u][0] = h0; hs[u][1] = h1; hs[u][2] = h2; hs[u][3] = h3;
            hs[u][4] = h4; hs[u][5] = h5; hs[u][6] = h6; hs[u][7] = h7;
            ull a0 = fma2a(whh[0][0], h0, xpdpk[u][0]);
            ull a1 = fma2a(whh[1][0], h0, xpdpk[u][1]);
            ull a2 = fma2a(whh[2][0], h0, xpdpk[u][2]);
            ull a3 = fma2a(whh[3][0], h0, xpdpk[u][3]);
            ull b0a = mul2(whh[0][1], h1), b1a = mul2(whh[1][1], h1),
                b2a = mul2(whh[2][1], h1), b3a = mul2(whh[3][1], h1);
            fma2(a0, whh[0][2], h2); fma2(a1, whh[1][2], h2);
            fma2(a2, whh[2][2], h2); fma2(a3, whh[3][2], h2);
            fma2(b0a, whh[0][3], h3); fma2(b1a, whh[1][3], h3);
            fma2(b2a, whh[2][3], h3); fma2(b3a, whh[3][3], h3);
            fma2(a0, whh[0][4], h4); fma2(a1, whh[1][4], h4);
            fma2(a2, whh[2][4], h4); fma2(a3, whh[3][4], h4);
            fma2(b0a, whh[0][5], h5); fma2(b1a, whh[1][5], h5);
            fma2(b2a, whh[2][5], h5); fma2(b3a, whh[3][5], h5);
            fma2(a0, whh[0][6], h6); fma2(a1, whh[1][6], h6);
            fma2(a2, whh[2][6], h6); fma2(a3, whh[3][6], h6);
            fma2(b0a, whh[0][7], h7); fma2(b1a, whh[1][7], h7);
            fma2(b2a, whh[2][7], h7); fma2(b3a, whh[3][7], h7);
            hh[u] = gates(add2(a0, b0a), add2(a1, b1a),
                          add2(a2, b2a), add2(a3, b3a), cs[u]);
        }
        #pragma unroll
        for (int u = 0; u < CH; ++u) hbuf[rb ^ 1][e0 + u][j] = hh[u];
        // tail filler: output row for t-1 from still-live h(t-1) regs
        if (doOut) {
            #pragma unroll
            for (int u = 0; u < CH; ++u) {
                ull oacc = fma2a(owp[0], hs[u][0], outbpk);
                #pragma unroll
                for (int p = 1; p < 8; ++p) fma2(oacc, owp[p], hs[u][p]);
                if (j < 8) po[u * OSTRIDE] = redu(oacc);
            }
            po += Fsz;
        }
        __syncwarp();
    };

    dstep(0, false);   // t=0 (no previous h to emit)
    dstep(1, true);    // t=1, emits row 0
    #pragma unroll 1
    for (int t = 2; t < Tsz; t += 2) {
        dstep(0, true);
        dstep(1, true);
    }
    // emit final row (h_{511} in hbuf[0])
    #pragma unroll
    for (int u = 0; u < CH; ++u) {
        const ull* hr = reinterpret_cast<const ull*>(&hbuf[0][e0 + u][0]);
        ull oacc = fma2a(owp[0], hr[0], outbpk);
        #pragma unroll
        for (int p = 1; p < 8; ++p) fma2(oacc, owp[p], hr[p]);
        if (j < 8) po[u * OSTRIDE] = redu(oacc);
    }
}

extern "C" void kernel_launch(void* const* d_in, const int* in_sizes, int n_in,
                              void* d_out, int out_size) {
    (void)in_sizes; (void)n_in; (void)out_size;
    lstm_ae<<<Bsz / EPB, THREADS>>>(
        (const float*)d_in[0],
        (const float*)d_in[1], (const float*)d_in[2],
        (const float*)d_in[3], (const float*)d_in[4],
        (const float*)d_in[5], (const float*)d_in[6],
        (const float*)d_in[7], (const float*)d_in[8],
        (const float*)d_in[9], (const float*)d_in[10],
        (float*)d_out);
}